// round 1
// baseline (speedup 1.0000x reference)
#include <cuda_runtime.h>
#include <cuda_bf16.h>

#define N_NODES 50000
#define N_EDGES 800000
#define DIM 128
#define NHEAD 8
#define EW 8  // warps (nodes) per block in k_edge

// ---------------- scratch (static device globals; no allocation) ----------------
__device__ float g_P[(size_t)N_NODES * NHEAD * DIM];   // per-node score projectors, 204.8MB
__device__ float g_c[N_NODES * NHEAD];                 // per-(node,head) score bias (q . b_K)
__device__ float g_WKT[DIM * DIM];                     // W_K transposed
__device__ int   g_counts[N_NODES];
__device__ int   g_offsets[N_NODES + 1];
__device__ int   g_cursor[N_NODES];
__device__ int   g_perm[N_EDGES];

// ---------------- CSR build ----------------
__global__ void k_zero() {
    int i = blockIdx.x * blockDim.x + threadIdx.x;
    if (i < N_NODES) g_counts[i] = 0;
}

__global__ void k_hist(const int* __restrict__ ei) {
    int e = blockIdx.x * blockDim.x + threadIdx.x;
    if (e < N_EDGES) atomicAdd(&g_counts[ei[N_EDGES + e]], 1);
}

// single-block exclusive scan over 50000 counts
__global__ void k_scan() {
    __shared__ int wsum[32];
    int t = threadIdx.x, lane = t & 31, wid = t >> 5;
    int carry = 0;
    for (int base = 0; base < N_NODES; base += 1024) {
        int i = base + t;
        int v = (i < N_NODES) ? g_counts[i] : 0;
        int x = v;
        #pragma unroll
        for (int o = 1; o < 32; o <<= 1) {
            int y = __shfl_up_sync(0xffffffffu, x, o);
            if (lane >= o) x += y;
        }
        if (lane == 31) wsum[wid] = x;
        __syncthreads();
        if (wid == 0) {
            int s = wsum[lane];
            #pragma unroll
            for (int o = 1; o < 32; o <<= 1) {
                int y = __shfl_up_sync(0xffffffffu, s, o);
                if (lane >= o) s += y;
            }
            wsum[lane] = s;
        }
        __syncthreads();
        int wexcl = wid ? wsum[wid - 1] : 0;
        int excl = x - v + wexcl;
        if (i < N_NODES) {
            g_offsets[i] = carry + excl;
            g_cursor[i]  = carry + excl;
        }
        carry += wsum[31];
        __syncthreads();
    }
    if (t == 0) g_offsets[N_NODES] = carry;
}

__global__ void k_scatter(const int* __restrict__ ei) {
    int e = blockIdx.x * blockDim.x + threadIdx.x;
    if (e < N_EDGES) {
        int j = ei[N_EDGES + e];
        int pos = atomicAdd(&g_cursor[j], 1);
        g_perm[pos] = e;
    }
}

// ---------------- node-side precompute ----------------
__global__ void k_wkt(const float* __restrict__ WK) {
    int i = blockIdx.x * blockDim.x + threadIdx.x;
    if (i < DIM * DIM) {
        int d = i / DIM, c = i % DIM;
        g_WKT[c * DIM + d] = WK[i];
    }
}

// q = x W_Q + b_Q;  P[n,h,:] = W_K[:,h-block] @ q_h;  c[n,h] = q_h . b_K_h
__global__ void k_qp(const float* __restrict__ x, const float* __restrict__ WQ,
                     const float* __restrict__ bQ, const float* __restrict__ bK) {
    __shared__ float sx[DIM], sq[DIM];
    int n = blockIdx.x, t = threadIdx.x;
    sx[t] = x[n * DIM + t];
    __syncthreads();
    float q = bQ[t];
    #pragma unroll 4
    for (int s = 0; s < DIM; s++) q = fmaf(sx[s], WQ[s * DIM + t], q);
    sq[t] = q;
    __syncthreads();
    #pragma unroll
    for (int h = 0; h < NHEAD; h++) {
        float acc = 0.f;
        #pragma unroll
        for (int k = 0; k < 16; k++)
            acc = fmaf(g_WKT[(h * 16 + k) * DIM + t], sq[h * 16 + k], acc);
        g_P[(size_t)n * (NHEAD * DIM) + h * DIM + t] = acc;
    }
    if (t < NHEAD) {
        float cc = 0.f;
        #pragma unroll
        for (int k = 0; k < 16; k++) cc = fmaf(sq[t * 16 + k], bK[t * 16 + k], cc);
        g_c[n * NHEAD + t] = cc;
    }
}

// ---------------- main fused edge pass + epilogue: one warp per node ----------------
__global__ void __launch_bounds__(256) k_edge(
    const float* __restrict__ ea, const float* __restrict__ elen,
    const float* __restrict__ WV, const float* __restrict__ bV,
    const float* __restrict__ WO, const float* __restrict__ bO,
    float* __restrict__ out)
{
    __shared__ float sU[EW][NHEAD * 130];  // padded rows: bank-conflict-free head reads
    __shared__ float sno[EW][DIM];
    __shared__ float ssc[EW][NHEAD];
    int w = threadIdx.x >> 5, l = threadIdx.x & 31;
    int n = blockIdx.x * EW + w;
    if (n >= N_NODES) return;

    // load P[n] into registers: lane l owns dims 4l..4l+3 for all 8 heads
    float4 P4[NHEAD];
    #pragma unroll
    for (int h = 0; h < NHEAD; h++)
        P4[h] = reinterpret_cast<const float4*>(g_P + (size_t)n * (NHEAD * DIM) + h * DIM)[l];
    float ch[NHEAD];
    #pragma unroll
    for (int h = 0; h < NHEAD; h++) ch[h] = g_c[n * NHEAD + h];

    float4 U[NHEAD];
    float ssum[NHEAD], tsum[NHEAD];
    #pragma unroll
    for (int h = 0; h < NHEAD; h++) {
        U[h] = make_float4(0.f, 0.f, 0.f, 0.f);
        ssum[h] = 0.f; tsum[h] = 0.f;
    }

    int beg = g_offsets[n], end = g_offsets[n + 1];
    const float KPI = 0.62831853071f;  // pi / CUTOFF

    // software-pipelined edge loop
    float4 a = make_float4(0.f, 0.f, 0.f, 0.f);
    float el = 0.f;
    if (beg < end) {
        int e0 = g_perm[beg];
        a = reinterpret_cast<const float4*>(ea + (size_t)e0 * DIM)[l];
        el = elen[e0];
    }
    for (int i = beg; i < end; i++) {
        float4 ac = a; float elc = el;
        if (i + 1 < end) {
            int en = g_perm[i + 1];
            a = reinterpret_cast<const float4*>(ea + (size_t)en * DIM)[l];
            el = elen[en];
        }
        float phi = 0.5f * __cosf(elc * KPI) + 0.5f;
        float p[NHEAD];
        #pragma unroll
        for (int h = 0; h < NHEAD; h++)
            p[h] = fmaf(ac.x, P4[h].x, fmaf(ac.y, P4[h].y, fmaf(ac.z, P4[h].z, ac.w * P4[h].w)));
        // butterfly-reduce 8 head scores across the warp (all lanes end identical)
        #pragma unroll
        for (int off = 16; off > 0; off >>= 1) {
            #pragma unroll
            for (int h = 0; h < NHEAD; h++)
                p[h] += __shfl_xor_sync(0xffffffffu, p[h], off);
        }
        #pragma unroll
        for (int h = 0; h < NHEAD; h++) {
            float ex = __expf((p[h] + ch[h]) * 0.25f);  // 1/sqrt(16); no max-sub needed (|s|<~6)
            ssum[h] += ex;
            float wh = ex * phi;
            tsum[h] += wh;
            U[h].x = fmaf(wh, ac.x, U[h].x);
            U[h].y = fmaf(wh, ac.y, U[h].y);
            U[h].z = fmaf(wh, ac.z, U[h].z);
            U[h].w = fmaf(wh, ac.w, U[h].w);
        }
    }

    // normalize, stage U to smem
    #pragma unroll
    for (int h = 0; h < NHEAD; h++) {
        float inv = (ssum[h] > 0.f) ? (1.0f / ssum[h]) : 0.f;
        sU[w][h * 130 + 4 * l + 0] = U[h].x * inv;
        sU[w][h * 130 + 4 * l + 1] = U[h].y * inv;
        sU[w][h * 130 + 4 * l + 2] = U[h].z * inv;
        sU[w][h * 130 + 4 * l + 3] = U[h].w * inv;
        if (l == 0) ssc[w][h] = tsum[h] * inv;  // sum of alpha*phi (for b_V term)
    }
    __syncwarp();

    // node_out[:, 4l..4l+3] = U_norm[h] @ W_V[:, cols] + (sum alpha*phi)*b_V
    int h = l >> 2;                       // 4l..4l+3 all in head h
    float tn = ssc[w][h];
    float4 bv = reinterpret_cast<const float4*>(bV)[l];
    float4 acc = make_float4(tn * bv.x, tn * bv.y, tn * bv.z, tn * bv.w);
    const float* sUh = &sU[w][h * 130];
    #pragma unroll 4
    for (int d = 0; d < DIM; d++) {
        float u = sUh[d];
        float4 wv = reinterpret_cast<const float4*>(WV + d * DIM)[l];
        acc.x = fmaf(u, wv.x, acc.x);
        acc.y = fmaf(u, wv.y, acc.y);
        acc.z = fmaf(u, wv.z, acc.z);
        acc.w = fmaf(u, wv.w, acc.w);
    }
    sno[w][4 * l + 0] = acc.x;
    sno[w][4 * l + 1] = acc.y;
    sno[w][4 * l + 2] = acc.z;
    sno[w][4 * l + 3] = acc.w;
    __syncwarp();

    // out = node_out @ W_O + b_O
    float4 o = reinterpret_cast<const float4*>(bO)[l];
    #pragma unroll 4
    for (int c = 0; c < DIM; c++) {
        float v = sno[w][c];
        float4 wo = reinterpret_cast<const float4*>(WO + c * DIM)[l];
        o.x = fmaf(v, wo.x, o.x);
        o.y = fmaf(v, wo.y, o.y);
        o.z = fmaf(v, wo.z, o.z);
        o.w = fmaf(v, wo.w, o.w);
    }
    reinterpret_cast<float4*>(out + (size_t)n * DIM)[l] = o;
}

// ---------------- launch ----------------
extern "C" void kernel_launch(void* const* d_in, const int* in_sizes, int n_in,
                              void* d_out, int out_size) {
    const float* x    = (const float*)d_in[0];
    const int*   ei   = (const int*)  d_in[1];
    const float* ea   = (const float*)d_in[2];
    const float* elen = (const float*)d_in[3];
    const float* WQ   = (const float*)d_in[4];
    const float* bQ   = (const float*)d_in[5];
    const float* WK   = (const float*)d_in[6];
    const float* bK   = (const float*)d_in[7];
    const float* WV   = (const float*)d_in[8];
    const float* bV   = (const float*)d_in[9];
    const float* WO   = (const float*)d_in[10];
    const float* bO   = (const float*)d_in[11];
    float* out = (float*)d_out;

    k_zero<<<(N_NODES + 255) / 256, 256>>>();
    k_hist<<<(N_EDGES + 255) / 256, 256>>>(ei);
    k_scan<<<1, 1024>>>();
    k_scatter<<<(N_EDGES + 255) / 256, 256>>>(ei);
    k_wkt<<<(DIM * DIM + 255) / 256, 256>>>(WK);
    k_qp<<<N_NODES, 128>>>(x, WQ, bQ, bK);
    k_edge<<<(N_NODES + EW - 1) / EW, 256>>>(ea, elen, WV, bV, WO, bO, out);
}

// round 2
// speedup vs baseline: 1.0298x; 1.0298x over previous
#include <cuda_runtime.h>
#include <cuda_bf16.h>

#define N_NODES 50000
#define N_EDGES 800000
#define DIM 128
#define NHEAD 8
#define EW 8  // warps (nodes) per block in k_edge

// ---------------- scratch (static device globals; no allocation) ----------------
__device__ float g_P[(size_t)N_NODES * NHEAD * DIM];   // per-node score projectors, 204.8MB
__device__ float g_c[N_NODES * NHEAD];                 // per-(node,head) score bias (q . b_K)
__device__ float g_WKT[DIM * DIM];                     // W_K transposed
__device__ int   g_counts[N_NODES];
__device__ int   g_offsets[N_NODES + 1];
__device__ int   g_cursor[N_NODES];
__device__ int   g_perm[N_EDGES];

// ---------------- CSR build ----------------
__global__ void k_zero() {
    int i = blockIdx.x * blockDim.x + threadIdx.x;
    if (i < N_NODES) g_counts[i] = 0;
}

__global__ void k_hist(const int* __restrict__ ei) {
    int e = blockIdx.x * blockDim.x + threadIdx.x;
    if (e < N_EDGES) atomicAdd(&g_counts[ei[N_EDGES + e]], 1);
}

// single-block exclusive scan over 50000 counts
__global__ void k_scan() {
    __shared__ int wsum[32];
    int t = threadIdx.x, lane = t & 31, wid = t >> 5;
    int carry = 0;
    for (int base = 0; base < N_NODES; base += 1024) {
        int i = base + t;
        int v = (i < N_NODES) ? g_counts[i] : 0;
        int x = v;
        #pragma unroll
        for (int o = 1; o < 32; o <<= 1) {
            int y = __shfl_up_sync(0xffffffffu, x, o);
            if (lane >= o) x += y;
        }
        if (lane == 31) wsum[wid] = x;
        __syncthreads();
        if (wid == 0) {
            int s = wsum[lane];
            #pragma unroll
            for (int o = 1; o < 32; o <<= 1) {
                int y = __shfl_up_sync(0xffffffffu, s, o);
                if (lane >= o) s += y;
            }
            wsum[lane] = s;
        }
        __syncthreads();
        int wexcl = wid ? wsum[wid - 1] : 0;
        int excl = x - v + wexcl;
        if (i < N_NODES) {
            g_offsets[i] = carry + excl;
            g_cursor[i]  = carry + excl;
        }
        carry += wsum[31];
        __syncthreads();
    }
    if (t == 0) g_offsets[N_NODES] = carry;
}

__global__ void k_scatter(const int* __restrict__ ei) {
    int e = blockIdx.x * blockDim.x + threadIdx.x;
    if (e < N_EDGES) {
        int j = ei[N_EDGES + e];
        int pos = atomicAdd(&g_cursor[j], 1);
        g_perm[pos] = e;
    }
}

// ---------------- node-side precompute ----------------
__global__ void k_wkt(const float* __restrict__ WK) {
    int i = blockIdx.x * blockDim.x + threadIdx.x;
    if (i < DIM * DIM) {
        int d = i / DIM, c = i % DIM;
        g_WKT[c * DIM + d] = WK[i];
    }
}

// q = x W_Q + b_Q;  P[n,h,:] = W_K[:,h-block] @ q_h;  c[n,h] = q_h . b_K_h
__global__ void k_qp(const float* __restrict__ x, const float* __restrict__ WQ,
                     const float* __restrict__ bQ, const float* __restrict__ bK) {
    __shared__ float sx[DIM], sq[DIM];
    int n = blockIdx.x, t = threadIdx.x;
    sx[t] = x[n * DIM + t];
    __syncthreads();
    float q = bQ[t];
    #pragma unroll 4
    for (int s = 0; s < DIM; s++) q = fmaf(sx[s], WQ[s * DIM + t], q);
    sq[t] = q;
    __syncthreads();
    #pragma unroll
    for (int h = 0; h < NHEAD; h++) {
        float acc = 0.f;
        #pragma unroll
        for (int k = 0; k < 16; k++)
            acc = fmaf(g_WKT[(h * 16 + k) * DIM + t], sq[h * 16 + k], acc);
        g_P[(size_t)n * (NHEAD * DIM) + h * DIM + t] = acc;
    }
    if (t < NHEAD) {
        float cc = 0.f;
        #pragma unroll
        for (int k = 0; k < 16; k++) cc = fmaf(sq[t * 16 + k], bK[t * 16 + k], cc);
        g_c[n * NHEAD + t] = cc;
    }
}

// ---------------- main fused edge pass + epilogue: one warp per node ----------------
__global__ void __launch_bounds__(256) k_edge(
    const float* __restrict__ ea, const float* __restrict__ elen,
    const float* __restrict__ WV, const float* __restrict__ bV,
    const float* __restrict__ WO, const float* __restrict__ bO,
    float* __restrict__ out)
{
    __shared__ float sU[EW][NHEAD * 130];  // padded rows: bank-conflict-free head reads
    __shared__ float sno[EW][DIM];
    __shared__ float ssc[EW][NHEAD];
    int w = threadIdx.x >> 5, l = threadIdx.x & 31;
    int n = blockIdx.x * EW + w;
    if (n >= N_NODES) return;

    // load P[n] into registers: lane l owns dims 4l..4l+3 for all 8 heads
    float4 P4[NHEAD];
    #pragma unroll
    for (int h = 0; h < NHEAD; h++)
        P4[h] = reinterpret_cast<const float4*>(g_P + (size_t)n * (NHEAD * DIM) + h * DIM)[l];
    float ch[NHEAD];
    #pragma unroll
    for (int h = 0; h < NHEAD; h++) ch[h] = g_c[n * NHEAD + h];

    float4 U[NHEAD];
    float ssum[NHEAD], tsum[NHEAD];
    #pragma unroll
    for (int h = 0; h < NHEAD; h++) {
        U[h] = make_float4(0.f, 0.f, 0.f, 0.f);
        ssum[h] = 0.f; tsum[h] = 0.f;
    }

    int beg = g_offsets[n], end = g_offsets[n + 1];
    const float KPI = 0.62831853071f;  // pi / CUTOFF

    // software-pipelined edge loop
    float4 a = make_float4(0.f, 0.f, 0.f, 0.f);
    float el = 0.f;
    if (beg < end) {
        int e0 = g_perm[beg];
        a = reinterpret_cast<const float4*>(ea + (size_t)e0 * DIM)[l];
        el = elen[e0];
    }
    for (int i = beg; i < end; i++) {
        float4 ac = a; float elc = el;
        if (i + 1 < end) {
            int en = g_perm[i + 1];
            a = reinterpret_cast<const float4*>(ea + (size_t)en * DIM)[l];
            el = elen[en];
        }
        float phi = 0.5f * __cosf(elc * KPI) + 0.5f;
        float p[NHEAD];
        #pragma unroll
        for (int h = 0; h < NHEAD; h++)
            p[h] = fmaf(ac.x, P4[h].x, fmaf(ac.y, P4[h].y, fmaf(ac.z, P4[h].z, ac.w * P4[h].w)));
        // butterfly-reduce 8 head scores across the warp (all lanes end identical)
        #pragma unroll
        for (int off = 16; off > 0; off >>= 1) {
            #pragma unroll
            for (int h = 0; h < NHEAD; h++)
                p[h] += __shfl_xor_sync(0xffffffffu, p[h], off);
        }
        #pragma unroll
        for (int h = 0; h < NHEAD; h++) {
            float ex = __expf((p[h] + ch[h]) * 0.25f);  // 1/sqrt(16); no max-sub needed (|s|<~6)
            ssum[h] += ex;
            float wh = ex * phi;
            tsum[h] += wh;
            U[h].x = fmaf(wh, ac.x, U[h].x);
            U[h].y = fmaf(wh, ac.y, U[h].y);
            U[h].z = fmaf(wh, ac.z, U[h].z);
            U[h].w = fmaf(wh, ac.w, U[h].w);
        }
    }

    // normalize, stage U to smem
    #pragma unroll
    for (int h = 0; h < NHEAD; h++) {
        float inv = (ssum[h] > 0.f) ? (1.0f / ssum[h]) : 0.f;
        sU[w][h * 130 + 4 * l + 0] = U[h].x * inv;
        sU[w][h * 130 + 4 * l + 1] = U[h].y * inv;
        sU[w][h * 130 + 4 * l + 2] = U[h].z * inv;
        sU[w][h * 130 + 4 * l + 3] = U[h].w * inv;
        if (l == 0) ssc[w][h] = tsum[h] * inv;  // sum of alpha*phi (for b_V term)
    }
    __syncwarp();

    // node_out[:, 4l..4l+3] = U_norm[h] @ W_V[:, cols] + (sum alpha*phi)*b_V
    int h = l >> 2;                       // 4l..4l+3 all in head h
    float tn = ssc[w][h];
    float4 bv = reinterpret_cast<const float4*>(bV)[l];
    float4 acc = make_float4(tn * bv.x, tn * bv.y, tn * bv.z, tn * bv.w);
    const float* sUh = &sU[w][h * 130];
    #pragma unroll 4
    for (int d = 0; d < DIM; d++) {
        float u = sUh[d];
        float4 wv = reinterpret_cast<const float4*>(WV + d * DIM)[l];
        acc.x = fmaf(u, wv.x, acc.x);
        acc.y = fmaf(u, wv.y, acc.y);
        acc.z = fmaf(u, wv.z, acc.z);
        acc.w = fmaf(u, wv.w, acc.w);
    }
    sno[w][4 * l + 0] = acc.x;
    sno[w][4 * l + 1] = acc.y;
    sno[w][4 * l + 2] = acc.z;
    sno[w][4 * l + 3] = acc.w;
    __syncwarp();

    // out = node_out @ W_O + b_O
    float4 o = reinterpret_cast<const float4*>(bO)[l];
    #pragma unroll 4
    for (int c = 0; c < DIM; c++) {
        float v = sno[w][c];
        float4 wo = reinterpret_cast<const float4*>(WO + c * DIM)[l];
        o.x = fmaf(v, wo.x, o.x);
        o.y = fmaf(v, wo.y, o.y);
        o.z = fmaf(v, wo.z, o.z);
        o.w = fmaf(v, wo.w, o.w);
    }
    reinterpret_cast<float4*>(out + (size_t)n * DIM)[l] = o;
}

// ---------------- launch ----------------
extern "C" void kernel_launch(void* const* d_in, const int* in_sizes, int n_in,
                              void* d_out, int out_size) {
    const float* x    = (const float*)d_in[0];
    const int*   ei   = (const int*)  d_in[1];
    const float* ea   = (const float*)d_in[2];
    const float* elen = (const float*)d_in[3];
    const float* WQ   = (const float*)d_in[4];
    const float* bQ   = (const float*)d_in[5];
    const float* WK   = (const float*)d_in[6];
    const float* bK   = (const float*)d_in[7];
    const float* WV   = (const float*)d_in[8];
    const float* bV   = (const float*)d_in[9];
    const float* WO   = (const float*)d_in[10];
    const float* bO   = (const float*)d_in[11];
    float* out = (float*)d_out;

    k_zero<<<(N_NODES + 255) / 256, 256>>>();
    k_hist<<<(N_EDGES + 255) / 256, 256>>>(ei);
    k_scan<<<1, 1024>>>();
    k_scatter<<<(N_EDGES + 255) / 256, 256>>>(ei);
    k_wkt<<<(DIM * DIM + 255) / 256, 256>>>(WK);
    k_qp<<<N_NODES, 128>>>(x, WQ, bQ, bK);
    k_edge<<<(N_NODES + EW - 1) / EW, 256>>>(ea, elen, WV, bV, WO, bO, out);
}

// round 3
// speedup vs baseline: 1.0310x; 1.0012x over previous
#include <cuda_runtime.h>
#include <cuda_bf16.h>

#define N_NODES 50000
#define N_EDGES 800000
#define DIM 128
#define NHEAD 8
#define EW 8  // warps (nodes) per block in k_edge

// ---------------- scratch (static device globals; no allocation) ----------------
__device__ float g_P[(size_t)N_NODES * NHEAD * DIM];   // per-node score projectors, 204.8MB
__device__ float g_c[N_NODES * NHEAD];                 // per-(node,head) score bias (q . b_K)
__device__ float g_WKT[DIM * DIM];                     // W_K transposed
__device__ int   g_counts[N_NODES];
__device__ int   g_offsets[N_NODES + 1];
__device__ int   g_cursor[N_NODES];
__device__ int   g_perm[N_EDGES];

// ---------------- CSR build ----------------
__global__ void k_zero() {
    int i = blockIdx.x * blockDim.x + threadIdx.x;
    if (i < N_NODES) g_counts[i] = 0;
}

__global__ void k_hist(const int* __restrict__ ei) {
    int e = blockIdx.x * blockDim.x + threadIdx.x;
    if (e < N_EDGES) atomicAdd(&g_counts[ei[N_EDGES + e]], 1);
}

// single-block exclusive scan over 50000 counts
__global__ void k_scan() {
    __shared__ int wsum[32];
    int t = threadIdx.x, lane = t & 31, wid = t >> 5;
    int carry = 0;
    for (int base = 0; base < N_NODES; base += 1024) {
        int i = base + t;
        int v = (i < N_NODES) ? g_counts[i] : 0;
        int x = v;
        #pragma unroll
        for (int o = 1; o < 32; o <<= 1) {
            int y = __shfl_up_sync(0xffffffffu, x, o);
            if (lane >= o) x += y;
        }
        if (lane == 31) wsum[wid] = x;
        __syncthreads();
        if (wid == 0) {
            int s = wsum[lane];
            #pragma unroll
            for (int o = 1; o < 32; o <<= 1) {
                int y = __shfl_up_sync(0xffffffffu, s, o);
                if (lane >= o) s += y;
            }
            wsum[lane] = s;
        }
        __syncthreads();
        int wexcl = wid ? wsum[wid - 1] : 0;
        int excl = x - v + wexcl;
        if (i < N_NODES) {
            g_offsets[i] = carry + excl;
            g_cursor[i]  = carry + excl;
        }
        carry += wsum[31];
        __syncthreads();
    }
    if (t == 0) g_offsets[N_NODES] = carry;
}

__global__ void k_scatter(const int* __restrict__ ei) {
    int e = blockIdx.x * blockDim.x + threadIdx.x;
    if (e < N_EDGES) {
        int j = ei[N_EDGES + e];
        int pos = atomicAdd(&g_cursor[j], 1);
        g_perm[pos] = e;
    }
}

// ---------------- node-side precompute ----------------
__global__ void k_wkt(const float* __restrict__ WK) {
    int i = blockIdx.x * blockDim.x + threadIdx.x;
    if (i < DIM * DIM) {
        int d = i / DIM, c = i % DIM;
        g_WKT[c * DIM + d] = WK[i];
    }
}

// q = x W_Q + b_Q;  P[n,h,:] = W_K[:,h-block] @ q_h;  c[n,h] = q_h . b_K_h
__global__ void k_qp(const float* __restrict__ x, const float* __restrict__ WQ,
                     const float* __restrict__ bQ, const float* __restrict__ bK) {
    __shared__ float sx[DIM], sq[DIM];
    int n = blockIdx.x, t = threadIdx.x;
    sx[t] = x[n * DIM + t];
    __syncthreads();
    float q = bQ[t];
    #pragma unroll 4
    for (int s = 0; s < DIM; s++) q = fmaf(sx[s], WQ[s * DIM + t], q);
    sq[t] = q;
    __syncthreads();
    #pragma unroll
    for (int h = 0; h < NHEAD; h++) {
        float acc = 0.f;
        #pragma unroll
        for (int k = 0; k < 16; k++)
            acc = fmaf(g_WKT[(h * 16 + k) * DIM + t], sq[h * 16 + k], acc);
        g_P[(size_t)n * (NHEAD * DIM) + h * DIM + t] = acc;
    }
    if (t < NHEAD) {
        float cc = 0.f;
        #pragma unroll
        for (int k = 0; k < 16; k++) cc = fmaf(sq[t * 16 + k], bK[t * 16 + k], cc);
        g_c[n * NHEAD + t] = cc;
    }
}

// ---------------- main fused edge pass + epilogue: one warp per node ----------------
__global__ void __launch_bounds__(256) k_edge(
    const float* __restrict__ ea, const float* __restrict__ elen,
    const float* __restrict__ WV, const float* __restrict__ bV,
    const float* __restrict__ WO, const float* __restrict__ bO,
    float* __restrict__ out)
{
    __shared__ float sU[EW][NHEAD * 130];  // padded rows: bank-conflict-free head reads
    __shared__ float sno[EW][DIM];
    __shared__ float ssc[EW][NHEAD];
    int w = threadIdx.x >> 5, l = threadIdx.x & 31;
    int n = blockIdx.x * EW + w;
    if (n >= N_NODES) return;

    // load P[n] into registers: lane l owns dims 4l..4l+3 for all 8 heads
    float4 P4[NHEAD];
    #pragma unroll
    for (int h = 0; h < NHEAD; h++)
        P4[h] = reinterpret_cast<const float4*>(g_P + (size_t)n * (NHEAD * DIM) + h * DIM)[l];
    float ch[NHEAD];
    #pragma unroll
    for (int h = 0; h < NHEAD; h++) ch[h] = g_c[n * NHEAD + h];

    float4 U[NHEAD];
    float ssum[NHEAD], tsum[NHEAD];
    #pragma unroll
    for (int h = 0; h < NHEAD; h++) {
        U[h] = make_float4(0.f, 0.f, 0.f, 0.f);
        ssum[h] = 0.f; tsum[h] = 0.f;
    }

    int beg = g_offsets[n], end = g_offsets[n + 1];
    const float KPI = 0.62831853071f;  // pi / CUTOFF

    // software-pipelined edge loop
    float4 a = make_float4(0.f, 0.f, 0.f, 0.f);
    float el = 0.f;
    if (beg < end) {
        int e0 = g_perm[beg];
        a = reinterpret_cast<const float4*>(ea + (size_t)e0 * DIM)[l];
        el = elen[e0];
    }
    for (int i = beg; i < end; i++) {
        float4 ac = a; float elc = el;
        if (i + 1 < end) {
            int en = g_perm[i + 1];
            a = reinterpret_cast<const float4*>(ea + (size_t)en * DIM)[l];
            el = elen[en];
        }
        float phi = 0.5f * __cosf(elc * KPI) + 0.5f;
        float p[NHEAD];
        #pragma unroll
        for (int h = 0; h < NHEAD; h++)
            p[h] = fmaf(ac.x, P4[h].x, fmaf(ac.y, P4[h].y, fmaf(ac.z, P4[h].z, ac.w * P4[h].w)));
        // butterfly-reduce 8 head scores across the warp (all lanes end identical)
        #pragma unroll
        for (int off = 16; off > 0; off >>= 1) {
            #pragma unroll
            for (int h = 0; h < NHEAD; h++)
                p[h] += __shfl_xor_sync(0xffffffffu, p[h], off);
        }
        #pragma unroll
        for (int h = 0; h < NHEAD; h++) {
            float ex = __expf((p[h] + ch[h]) * 0.25f);  // 1/sqrt(16); no max-sub needed (|s|<~6)
            ssum[h] += ex;
            float wh = ex * phi;
            tsum[h] += wh;
            U[h].x = fmaf(wh, ac.x, U[h].x);
            U[h].y = fmaf(wh, ac.y, U[h].y);
            U[h].z = fmaf(wh, ac.z, U[h].z);
            U[h].w = fmaf(wh, ac.w, U[h].w);
        }
    }

    // normalize, stage U to smem
    #pragma unroll
    for (int h = 0; h < NHEAD; h++) {
        float inv = (ssum[h] > 0.f) ? (1.0f / ssum[h]) : 0.f;
        sU[w][h * 130 + 4 * l + 0] = U[h].x * inv;
        sU[w][h * 130 + 4 * l + 1] = U[h].y * inv;
        sU[w][h * 130 + 4 * l + 2] = U[h].z * inv;
        sU[w][h * 130 + 4 * l + 3] = U[h].w * inv;
        if (l == 0) ssc[w][h] = tsum[h] * inv;  // sum of alpha*phi (for b_V term)
    }
    __syncwarp();

    // node_out[:, 4l..4l+3] = U_norm[h] @ W_V[:, cols] + (sum alpha*phi)*b_V
    int h = l >> 2;                       // 4l..4l+3 all in head h
    float tn = ssc[w][h];
    float4 bv = reinterpret_cast<const float4*>(bV)[l];
    float4 acc = make_float4(tn * bv.x, tn * bv.y, tn * bv.z, tn * bv.w);
    const float* sUh = &sU[w][h * 130];
    #pragma unroll 4
    for (int d = 0; d < DIM; d++) {
        float u = sUh[d];
        float4 wv = reinterpret_cast<const float4*>(WV + d * DIM)[l];
        acc.x = fmaf(u, wv.x, acc.x);
        acc.y = fmaf(u, wv.y, acc.y);
        acc.z = fmaf(u, wv.z, acc.z);
        acc.w = fmaf(u, wv.w, acc.w);
    }
    sno[w][4 * l + 0] = acc.x;
    sno[w][4 * l + 1] = acc.y;
    sno[w][4 * l + 2] = acc.z;
    sno[w][4 * l + 3] = acc.w;
    __syncwarp();

    // out = node_out @ W_O + b_O
    float4 o = reinterpret_cast<const float4*>(bO)[l];
    #pragma unroll 4
    for (int c = 0; c < DIM; c++) {
        float v = sno[w][c];
        float4 wo = reinterpret_cast<const float4*>(WO + c * DIM)[l];
        o.x = fmaf(v, wo.x, o.x);
        o.y = fmaf(v, wo.y, o.y);
        o.z = fmaf(v, wo.z, o.z);
        o.w = fmaf(v, wo.w, o.w);
    }
    reinterpret_cast<float4*>(out + (size_t)n * DIM)[l] = o;
}

// ---------------- launch ----------------
extern "C" void kernel_launch(void* const* d_in, const int* in_sizes, int n_in,
                              void* d_out, int out_size) {
    const float* x    = (const float*)d_in[0];
    const int*   ei   = (const int*)  d_in[1];
    const float* ea   = (const float*)d_in[2];
    const float* elen = (const float*)d_in[3];
    const float* WQ   = (const float*)d_in[4];
    const float* bQ   = (const float*)d_in[5];
    const float* WK   = (const float*)d_in[6];
    const float* bK   = (const float*)d_in[7];
    const float* WV   = (const float*)d_in[8];
    const float* bV   = (const float*)d_in[9];
    const float* WO   = (const float*)d_in[10];
    const float* bO   = (const float*)d_in[11];
    float* out = (float*)d_out;

    k_zero<<<(N_NODES + 255) / 256, 256>>>();
    k_hist<<<(N_EDGES + 255) / 256, 256>>>(ei);
    k_scan<<<1, 1024>>>();
    k_scatter<<<(N_EDGES + 255) / 256, 256>>>(ei);
    k_wkt<<<(DIM * DIM + 255) / 256, 256>>>(WK);
    k_qp<<<N_NODES, 128>>>(x, WQ, bQ, bK);
    k_edge<<<(N_NODES + EW - 1) / EW, 256>>>(ea, elen, WV, bV, WO, bO, out);
}